// round 1
// baseline (speedup 1.0000x reference)
#include <cuda_runtime.h>

// ActionNetwork: B=262144 rows, N=8, M=1.
// Per row: 80 f32 in -> 128 f32 out. Pure HBM-streaming problem.
// Design: coalesced smem staging on both input and output to keep l1tex
// wavefront cost ~10x below the DRAM floor.

constexpr int TPB = 256;
constexpr int ROW = 80;          // floats per input row
constexpr int OROW = 128;        // floats per output row
constexpr int INSTRIDE = 84;     // input smem row stride (floats), 16B-aligned, LDS128 conflict-free
constexpr int OUTSTRIDE = 132;   // output smem row stride (floats), 16B-aligned, STS128 conflict-free

// dynamic smem layout (in floats)
constexpr int SM_IN = 0;                         // 256*84 = 21504
constexpr int SM_OUT = TPB * INSTRIDE;           // 128*132 = 16896
constexpr int SM_PAR = SM_OUT + 128 * OUTSTRIDE; // params base = 38400
// params layout within SM_PAR:
constexpr int P_W0 = 0;        // 8 rows x 20 (padded from 18) = 160
constexpr int P_B0 = 160;      // 8
constexpr int P_W1 = 168;      // 64
constexpr int P_B1 = 232;      // 8
constexpr int P_DIST = 240;    // 64
constexpr int P_QP = 304;      // 64
constexpr int P_DEP = 368;     // 64
constexpr int P_ARR = 432;     // 64
constexpr int P_MINIF = 496;   // 8
constexpr int P_INTF = 504;    // 64
constexpr int P_PRICE = 568;   // 64
constexpr int P_TOTAL = 632;
constexpr int SMEM_FLOATS = SM_PAR + P_TOTAL;    // 39032
constexpr int SMEM_BYTES = SMEM_FLOATS * 4;      // 156128

__global__ __launch_bounds__(TPB, 1)
void actnet_kernel(const float* __restrict__ x,
                   const float* __restrict__ W0, const float* __restrict__ b0,
                   const float* __restrict__ W1, const float* __restrict__ b1,
                   const float* __restrict__ distp, const float* __restrict__ qp,
                   const float* __restrict__ depf, const float* __restrict__ arrf,
                   const float* __restrict__ minif, const float* __restrict__ intf,
                   const float* __restrict__ pricef,
                   float* __restrict__ out)
{
    extern __shared__ float sm[];
    const int tid = threadIdx.x;
    const int blk = blockIdx.x;

    // ---- stage params into smem (broadcast source reads, once per block) ----
    float* Wp = sm + SM_PAR;
    for (int idx = tid; idx < 144; idx += TPB)
        Wp[P_W0 + (idx / 18) * 20 + (idx % 18)] = W0[idx];
    for (int idx = tid; idx < 16; idx += TPB)
        Wp[P_W0 + (idx >> 1) * 20 + 18 + (idx & 1)] = 0.0f;   // zero the padding
    for (int idx = tid; idx < 8; idx += TPB) {
        Wp[P_B0 + idx] = b0[idx];
        Wp[P_B1 + idx] = b1[idx];
        Wp[P_MINIF + idx] = minif[idx];
    }
    for (int idx = tid; idx < 64; idx += TPB) {
        Wp[P_W1 + idx] = W1[idx];
        Wp[P_DIST + idx] = distp[idx];
        Wp[P_QP + idx] = qp[idx];
        Wp[P_DEP + idx] = depf[idx];
        Wp[P_ARR + idx] = arrf[idx];
        Wp[P_INTF + idx] = intf[idx];
        Wp[P_PRICE + idx] = pricef[idx];
    }

    // ---- stage input: fully coalesced float4 loads -> padded smem rows ----
    const float4* x4 = (const float4*)x + (size_t)blk * (TPB * ROW / 4);
    #pragma unroll
    for (int k = 0; k < ROW / 4; k++) {            // 20 iterations
        int g = tid + k * TPB;
        float4 v = __ldg(&x4[g]);
        int row = g / 20;
        int col = (g % 20) * 4;
        *(float4*)&sm[SM_IN + row * INSTRIDE + col] = v;
    }
    __syncthreads();

    const float* myrow = &sm[SM_IN + tid * INSTRIDE];

    // vehicle, mini
    float veh[8], mini[8];
    {
        float4 v0 = *(const float4*)&myrow[0];
        float4 v1 = *(const float4*)&myrow[4];
        float4 m0 = *(const float4*)&myrow[8];
        float4 m1 = *(const float4*)&myrow[12];
        veh[0] = v0.x; veh[1] = v0.y; veh[2] = v0.z; veh[3] = v0.w;
        veh[4] = v1.x; veh[5] = v1.y; veh[6] = v1.z; veh[7] = v1.w;
        mini[0] = m0.x; mini[1] = m0.y; mini[2] = m0.z; mini[3] = m0.w;
        mini[4] = m1.x; mini[5] = m1.y; mini[6] = m1.z; mini[7] = m1.w;
    }

    // ---- p[i] = b0 + veh*W0[:,0] + mini*W0[:,1] + q[i,:].W0[i,2:10] + q[:,i].W0[:,10+r] ----
    float p[8];
    #pragma unroll
    for (int i = 0; i < 8; i++)
        p[i] = Wp[P_B0 + i] + veh[i] * Wp[P_W0 + i * 20 + 0] + mini[i] * Wp[P_W0 + i * 20 + 1];

    #pragma unroll
    for (int r = 0; r < 8; r++) {
        float4 q0 = *(const float4*)&myrow[16 + r * 8];
        float4 q1 = *(const float4*)&myrow[16 + r * 8 + 4];
        float qr[8] = {q0.x, q0.y, q0.z, q0.w, q1.x, q1.y, q1.z, q1.w};
        const float* w0r = &Wp[P_W0 + r * 20];
        #pragma unroll
        for (int c = 0; c < 8; c++) p[r] += qr[c] * w0r[2 + c];       // direct row
        #pragma unroll
        for (int i = 0; i < 8; i++) p[i] += qr[i] * Wp[P_W0 + i * 20 + 10 + r]; // transposed
    }

    // ---- potential = p @ W1^T + b1 ----
    float pot[8];
    #pragma unroll
    for (int i = 0; i < 8; i++) {
        float a = Wp[P_B1 + i];
        #pragma unroll
        for (int k = 0; k < 8; k++) a += p[k] * Wp[P_W1 + i * 8 + k];
        pot[i] = a;
    }

    // ---- gradient, tot, inv, scale ----
    float g[64];
    float inv[8], scale[8];
    #pragma unroll
    for (int i = 0; i < 8; i++) {
        float4 q0 = *(const float4*)&myrow[16 + i * 8];
        float4 q1 = *(const float4*)&myrow[16 + i * 8 + 4];
        float qr[8] = {q0.x, q0.y, q0.z, q0.w, q1.x, q1.y, q1.z, q1.w};
        const float* dr = &Wp[P_DIST + i * 8];
        const float* qpr = &Wp[P_QP + i * 8];
        float rs = 0.0f;
        #pragma unroll
        for (int j = 0; j < 8; j++) {
            float d = pot[i] - pot[j];
            float gv = fmaxf(d, 0.0f) * dr[j] + qr[j] * qpr[j];
            g[i * 8 + j] = gv;
            rs += gv;
        }
        float remain = fmaxf(veh[i] - rs, 0.0f);
        g[i * 8 + i] += remain;
        float tot = fmaxf(rs + remain - 0.001f, 0.0f) + 0.001f;
        inv[i] = 1.0f / tot;
        scale[i] = veh[i] * inv[i];
    }

    // ---- departure, arrival, intentions ----
    float arrival[8];
    #pragma unroll
    for (int j = 0; j < 8; j++) arrival[j] = mini[j] * Wp[P_MINIF + j];

    float departure[8], intents[8];
    #pragma unroll
    for (int i = 0; i < 8; i++) {
        const float* depr = &Wp[P_DEP + i * 8];
        const float* arrr = &Wp[P_ARR + i * 8];
        const float* intr = &Wp[P_INTF + i * 8];
        float sc = scale[i];
        float dsum = 0.0f, isum = 0.0f;
        #pragma unroll
        for (int j = 0; j < 8; j++) {
            float gv = g[i * 8 + j];
            float raw = gv * sc;
            dsum += raw * depr[j];
            arrival[j] += raw * arrr[j];
            float fg = fmaxf(gv - raw, 0.0f);
            isum += fg * intr[j];
        }
        departure[i] = dsum;
        intents[i] = isum;
    }

    float no_remain[8];
    #pragma unroll
    for (int i = 0; i < 8; i++) {
        float fv = veh[i] - departure[i] + arrival[i];
        no_remain[i] = fmaxf(fv - intents[i], 0.0f) * (1.0f / 7.0f);
    }

    // ---- output: two 128-row chunks, staged in smem, coalesced flush ----
    #pragma unroll 1
    for (int chunk = 0; chunk < 2; chunk++) {
        __syncthreads();
        if ((tid >> 7) == chunk) {
            float* orow = &sm[SM_OUT + (tid & 127) * OUTSTRIDE];
            #pragma unroll
            for (int i = 0; i < 8; i++) {
                const float* prf = &Wp[P_PRICE + i * 8];
                float sc = scale[i], iv = inv[i], nr = no_remain[i];
                float av[8], pv[8];
                #pragma unroll
                for (int j = 0; j < 8; j++) {
                    float gv = g[i * 8 + j];
                    av[j] = gv * iv;                              // action
                    float raw = gv * sc;                          // raw_action
                    float fg = fmaxf(gv - raw, 0.0f);             // future_gradient
                    float fq = fmaxf(myrow[16 + i * 8 + j] - raw, 0.0f); // future_queue
                    float it = fg + nr - fq;                      // intention
                    pv[j] = fmaxf(1.0f - fmaxf(it * prf[j], 0.0f) - 0.6f, 0.0f) + 0.6f;
                }
                *(float4*)&orow[i * 16 + 0]  = make_float4(av[0], av[1], av[2], av[3]);
                *(float4*)&orow[i * 16 + 4]  = make_float4(av[4], av[5], av[6], av[7]);
                *(float4*)&orow[i * 16 + 8]  = make_float4(pv[0], pv[1], pv[2], pv[3]);
                *(float4*)&orow[i * 16 + 12] = make_float4(pv[4], pv[5], pv[6], pv[7]);
            }
        }
        __syncthreads();
        // flush 128 rows * 128 floats = 4096 float4, fully coalesced
        float4* out4 = (float4*)out + ((size_t)blk * TPB + chunk * 128) * (OROW / 4);
        #pragma unroll
        for (int k = 0; k < 16; k++) {
            int g4 = tid + k * TPB;
            int lrow = g4 >> 5;
            int col4 = g4 & 31;
            out4[g4] = *(const float4*)&sm[SM_OUT + lrow * OUTSTRIDE + col4 * 4];
        }
    }
}

extern "C" void kernel_launch(void* const* d_in, const int* in_sizes, int n_in,
                              void* d_out, int out_size) {
    const float* x      = (const float*)d_in[0];
    const float* W0     = (const float*)d_in[1];
    const float* b0     = (const float*)d_in[2];
    const float* W1     = (const float*)d_in[3];
    const float* b1     = (const float*)d_in[4];
    const float* distp  = (const float*)d_in[5];
    const float* qp     = (const float*)d_in[6];
    const float* depf   = (const float*)d_in[7];
    const float* arrf   = (const float*)d_in[8];
    const float* minif  = (const float*)d_in[9];
    const float* intf   = (const float*)d_in[10];
    const float* pricef = (const float*)d_in[11];
    float* out = (float*)d_out;

    int B = in_sizes[0] / ROW;          // 262144
    int grid = B / TPB;                 // 1024 (B divisible by 256 for this problem)

    cudaFuncSetAttribute(actnet_kernel, cudaFuncAttributeMaxDynamicSharedMemorySize, SMEM_BYTES);
    actnet_kernel<<<grid, TPB, SMEM_BYTES>>>(x, W0, b0, W1, b1, distp, qp, depf, arrf,
                                             minif, intf, pricef, out);
}